// round 1
// baseline (speedup 1.0000x reference)
#include <cuda_runtime.h>
#include <math.h>

#define BB 4
#define NN 8192
#define ROWS (BB*NN)     // 32768
#define CIN 64
#define MID 64
#define COUT 128
#define KNB 16           // k neighbors
#define TILE 2048
#define EPSBN 1e-5f

// ---------------- scratch (static device globals; no allocation) ----------------
__device__ int   g_knn[ROWS*KNB];
__device__ float g_X [ROWS*CIN];
__device__ float g_Y1[ROWS*MID];
__device__ float g_Ag[ROWS*MID];
__device__ float g_Ya[ROWS*MID];
__device__ float g_Y2[ROWS*COUT];
__device__ float g_Ps1[256*MID],  g_Pq1[256*MID];
__device__ float g_Psa[256*MID],  g_Pqa[256*MID];
__device__ float g_Ps2[256*COUT], g_Pq2[256*COUT];
__device__ float g_A1[MID],  g_C1[MID];
__device__ float g_Aa[MID],  g_Ca[MID];
__device__ float g_A2[COUT], g_C2[COUT];

// ---------------- kNN: per-thread query, shared candidate tiles ----------------
__global__ void __launch_bounds__(256) k_knn(const float* __restrict__ coords)
{
    __shared__ float4 tile[TILE];   // (x,y,z,|c|^2)  32KB
    const int b = blockIdx.y;
    const int q = blockIdx.x * 256 + threadIdx.x;
    const float* cb = coords + (size_t)b * NN * 3;

    const float qx = cb[q*3+0], qy = cb[q*3+1], qz = cb[q*3+2];
    const float sqi = qx*qx + qy*qy + qz*qz;

    float bd[KNB];
    int   bi[KNB];
#pragma unroll
    for (int t = 0; t < KNB; ++t) { bd[t] = 3.0e38f; bi[t] = 0; }

    for (int t0 = 0; t0 < NN; t0 += TILE) {
        __syncthreads();
        for (int i = threadIdx.x; i < TILE; i += 256) {
            const int j = t0 + i;
            const float x = cb[j*3+0], y = cb[j*3+1], z = cb[j*3+2];
            tile[i] = make_float4(x, y, z, x*x + y*y + z*z);
        }
        __syncthreads();

#pragma unroll 4
        for (int i = 0; i < TILE; ++i) {
            const float4 cj = tile[i];
            float dot = qx*cj.x;
            dot = fmaf(qy, cj.y, dot);
            dot = fmaf(qz, cj.z, dot);
            float d = (sqi + cj.w) - 2.0f*dot;
            if (d < bd[KNB-1]) {
                int j = t0 + i;
#pragma unroll
                for (int t = 0; t < KNB; ++t) {
                    if (d < bd[t]) {
                        float td = bd[t]; bd[t] = d; d = td;
                        int   tj = bi[t]; bi[t] = j; j = tj;
                    }
                }
            }
        }
    }

    int* op = g_knn + ((size_t)(b*NN + q)) * KNB;
#pragma unroll
    for (int t = 0; t < KNB; ++t) op[t] = bi[t];
}

// ---------------- gather + mean: one warp per point ----------------
__global__ void __launch_bounds__(256) k_gather(const float* __restrict__ feats)
{
    const int row  = blockIdx.x * 8 + (threadIdx.x >> 5);
    const int lane = threadIdx.x & 31;
    const int b = row >> 13;                       // row / 8192
    const float* fb = feats + (size_t)b * NN * CIN;
    const int* ip = g_knn + (size_t)row * KNB;

    float2 acc = make_float2(0.f, 0.f);
#pragma unroll
    for (int m = 0; m < KNB; ++m) {
        const int id = ip[m];
        const float2 v = ((const float2*)(fb + (size_t)id * CIN))[lane];
        acc.x += v.x; acc.y += v.y;
    }
    ((float2*)(g_X + (size_t)row * CIN))[lane] =
        make_float2(acc.x * (1.0f/KNB), acc.y * (1.0f/KNB));
}

// ---------------- warp sum helper ----------------
__device__ __forceinline__ float warp_sum(float v) {
#pragma unroll
    for (int o = 16; o; o >>= 1) v += __shfl_xor_sync(0xffffffffu, v, o);
    return v;
}

// ---------------- MLP1: Y1 = X @ W1 + b1, accumulate per-channel stats ----------------
__global__ void __launch_bounds__(128) k_mlp1(const float* __restrict__ W,
                                              const float* __restrict__ bias)
{
    __shared__ float Ws[CIN*MID];
    __shared__ float wsum[4][MID], wsq[4][MID];
    const int tid = threadIdx.x;
    for (int i = tid; i < CIN*MID; i += 128) Ws[i] = W[i];
    __syncthreads();

    const int r = blockIdx.x * 128 + tid;
    float x[CIN];
    {
        const float4* xp = (const float4*)(g_X + (size_t)r * CIN);
#pragma unroll
        for (int i = 0; i < CIN/4; ++i) {
            float4 v = xp[i];
            x[4*i]=v.x; x[4*i+1]=v.y; x[4*i+2]=v.z; x[4*i+3]=v.w;
        }
    }
    const int warp = tid >> 5, lane = tid & 31;
    float4* yp = (float4*)(g_Y1 + (size_t)r * MID);
    const float4* W4 = (const float4*)Ws;
    const float4* b4 = (const float4*)bias;

#pragma unroll
    for (int g = 0; g < MID/4; ++g) {
        float4 acc = b4[g];
#pragma unroll
        for (int k = 0; k < CIN; ++k) {
            const float4 w = W4[k*(MID/4)+g];
            acc.x = fmaf(x[k], w.x, acc.x);
            acc.y = fmaf(x[k], w.y, acc.y);
            acc.z = fmaf(x[k], w.z, acc.z);
            acc.w = fmaf(x[k], w.w, acc.w);
        }
        yp[g] = acc;
        const float vs[4] = {acc.x, acc.y, acc.z, acc.w};
#pragma unroll
        for (int u = 0; u < 4; ++u) {
            const float s = warp_sum(vs[u]);
            const float qq = warp_sum(vs[u]*vs[u]);
            if (lane == 0) { wsum[warp][4*g+u] = s; wsq[warp][4*g+u] = qq; }
        }
    }
    __syncthreads();
    if (tid < MID) {
        g_Ps1[blockIdx.x*MID+tid] = wsum[0][tid]+wsum[1][tid]+wsum[2][tid]+wsum[3][tid];
        g_Pq1[blockIdx.x*MID+tid] = wsq [0][tid]+wsq [1][tid]+wsq [2][tid]+wsq [3][tid];
    }
}

// ---------------- BN finalize kernels (deterministic partial-sum reduce) ----------------
__global__ void k_stats1(const float* __restrict__ g, const float* __restrict__ be)
{
    const int c = threadIdx.x;
    float s = 0.f, q = 0.f;
    for (int i = 0; i < 256; ++i) { s += g_Ps1[i*MID+c]; q += g_Pq1[i*MID+c]; }
    const float m = s / (float)ROWS;
    const float v = q / (float)ROWS - m*m;
    const float a = g[c] / sqrtf(v + EPSBN);
    g_A1[c] = a; g_C1[c] = be[c] - m*a;
}
__global__ void k_statsa(const float* __restrict__ g, const float* __restrict__ be)
{
    const int c = threadIdx.x;
    float s = 0.f, q = 0.f;
    for (int i = 0; i < 256; ++i) { s += g_Psa[i*MID+c]; q += g_Pqa[i*MID+c]; }
    const float m = s / (float)ROWS;
    const float v = q / (float)ROWS - m*m;
    const float a = g[c] / sqrtf(v + EPSBN);
    g_Aa[c] = a; g_Ca[c] = be[c] - m*a;
}
__global__ void k_stats2(const float* __restrict__ g, const float* __restrict__ be)
{
    const int c = threadIdx.x;
    float s = 0.f, q = 0.f;
    for (int i = 0; i < 256; ++i) { s += g_Ps2[i*COUT+c]; q += g_Pq2[i*COUT+c]; }
    const float m = s / (float)ROWS;
    const float v = q / (float)ROWS - m*m;
    const float a = g[c] / sqrtf(v + EPSBN);
    g_A2[c] = a; g_C2[c] = be[c] - m*a;
}

// ---------------- MLPa: agg = relu(bn(Y1)); Ya = agg @ Wa + ba; stats ----------------
__global__ void __launch_bounds__(128) k_mlpa(const float* __restrict__ W,
                                              const float* __restrict__ bias)
{
    __shared__ float Ws[MID*MID];
    __shared__ float wsum[4][MID], wsq[4][MID];
    const int tid = threadIdx.x;
    for (int i = tid; i < MID*MID; i += 128) Ws[i] = W[i];
    __syncthreads();

    const int r = blockIdx.x * 128 + tid;
    float x[MID];
    {
        const float4* yp = (const float4*)(g_Y1 + (size_t)r * MID);
        float4* ap = (float4*)(g_Ag + (size_t)r * MID);
#pragma unroll
        for (int i = 0; i < MID/4; ++i) {
            float4 v = yp[i];
            float z0 = fmaxf(fmaf(g_A1[4*i+0], v.x, g_C1[4*i+0]), 0.f);
            float z1 = fmaxf(fmaf(g_A1[4*i+1], v.y, g_C1[4*i+1]), 0.f);
            float z2 = fmaxf(fmaf(g_A1[4*i+2], v.z, g_C1[4*i+2]), 0.f);
            float z3 = fmaxf(fmaf(g_A1[4*i+3], v.w, g_C1[4*i+3]), 0.f);
            ap[i] = make_float4(z0, z1, z2, z3);
            x[4*i]=z0; x[4*i+1]=z1; x[4*i+2]=z2; x[4*i+3]=z3;
        }
    }
    const int warp = tid >> 5, lane = tid & 31;
    float4* yp = (float4*)(g_Ya + (size_t)r * MID);
    const float4* W4 = (const float4*)Ws;
    const float4* b4 = (const float4*)bias;

#pragma unroll
    for (int g = 0; g < MID/4; ++g) {
        float4 acc = b4[g];
#pragma unroll
        for (int k = 0; k < MID; ++k) {
            const float4 w = W4[k*(MID/4)+g];
            acc.x = fmaf(x[k], w.x, acc.x);
            acc.y = fmaf(x[k], w.y, acc.y);
            acc.z = fmaf(x[k], w.z, acc.z);
            acc.w = fmaf(x[k], w.w, acc.w);
        }
        yp[g] = acc;
        const float vs[4] = {acc.x, acc.y, acc.z, acc.w};
#pragma unroll
        for (int u = 0; u < 4; ++u) {
            const float s = warp_sum(vs[u]);
            const float qq = warp_sum(vs[u]*vs[u]);
            if (lane == 0) { wsum[warp][4*g+u] = s; wsq[warp][4*g+u] = qq; }
        }
    }
    __syncthreads();
    if (tid < MID) {
        g_Psa[blockIdx.x*MID+tid] = wsum[0][tid]+wsum[1][tid]+wsum[2][tid]+wsum[3][tid];
        g_Pqa[blockIdx.x*MID+tid] = wsq [0][tid]+wsq [1][tid]+wsq [2][tid]+wsq [3][tid];
    }
}

// ---------------- MLP2: attn=sigmoid(relu(bn(Ya))); fused=agg*attn+agg; Y2=fused@W2+b2 ----------------
__global__ void __launch_bounds__(128) k_mlp2(const float* __restrict__ W,
                                              const float* __restrict__ bias)
{
    __shared__ float Ws[MID*COUT];          // 32KB
    __shared__ float wsum[4][COUT], wsq[4][COUT];
    const int tid = threadIdx.x;
    for (int i = tid; i < MID*COUT; i += 128) Ws[i] = W[i];
    __syncthreads();

    const int r = blockIdx.x * 128 + tid;
    float x[MID];
    {
        const float4* yp = (const float4*)(g_Ya + (size_t)r * MID);
        const float4* ap = (const float4*)(g_Ag + (size_t)r * MID);
#pragma unroll
        for (int i = 0; i < MID/4; ++i) {
            float4 y = yp[i];
            float4 a = ap[i];
            float t0 = fmaxf(fmaf(g_Aa[4*i+0], y.x, g_Ca[4*i+0]), 0.f);
            float t1 = fmaxf(fmaf(g_Aa[4*i+1], y.y, g_Ca[4*i+1]), 0.f);
            float t2 = fmaxf(fmaf(g_Aa[4*i+2], y.z, g_Ca[4*i+2]), 0.f);
            float t3 = fmaxf(fmaf(g_Aa[4*i+3], y.w, g_Ca[4*i+3]), 0.f);
            float s0 = 1.0f / (1.0f + expf(-t0));
            float s1 = 1.0f / (1.0f + expf(-t1));
            float s2 = 1.0f / (1.0f + expf(-t2));
            float s3 = 1.0f / (1.0f + expf(-t3));
            x[4*i+0] = fmaf(a.x, s0, a.x);
            x[4*i+1] = fmaf(a.y, s1, a.y);
            x[4*i+2] = fmaf(a.z, s2, a.z);
            x[4*i+3] = fmaf(a.w, s3, a.w);
        }
    }
    const int warp = tid >> 5, lane = tid & 31;
    float4* yp = (float4*)(g_Y2 + (size_t)r * COUT);
    const float4* W4 = (const float4*)Ws;
    const float4* b4 = (const float4*)bias;

#pragma unroll
    for (int g = 0; g < COUT/4; ++g) {
        float4 acc = b4[g];
#pragma unroll
        for (int k = 0; k < MID; ++k) {
            const float4 w = W4[k*(COUT/4)+g];
            acc.x = fmaf(x[k], w.x, acc.x);
            acc.y = fmaf(x[k], w.y, acc.y);
            acc.z = fmaf(x[k], w.z, acc.z);
            acc.w = fmaf(x[k], w.w, acc.w);
        }
        yp[g] = acc;
        const float vs[4] = {acc.x, acc.y, acc.z, acc.w};
#pragma unroll
        for (int u = 0; u < 4; ++u) {
            const float s = warp_sum(vs[u]);
            const float qq = warp_sum(vs[u]*vs[u]);
            if (lane == 0) { wsum[warp][4*g+u] = s; wsq[warp][4*g+u] = qq; }
        }
    }
    __syncthreads();
    if (tid < COUT) {
        g_Ps2[blockIdx.x*COUT+tid] = wsum[0][tid]+wsum[1][tid]+wsum[2][tid]+wsum[3][tid];
        g_Pq2[blockIdx.x*COUT+tid] = wsq [0][tid]+wsq [1][tid]+wsq [2][tid]+wsq [3][tid];
    }
}

// ---------------- final: out = relu(bn(Y2)) ----------------
__global__ void __launch_bounds__(256) k_final(float* __restrict__ out)
{
    const int i = blockIdx.x * 256 + threadIdx.x;
    const int c = i & (COUT-1);
    out[i] = fmaxf(fmaf(g_A2[c], g_Y2[i], g_C2[c]), 0.f);
}

// ---------------- launch ----------------
extern "C" void kernel_launch(void* const* d_in, const int* in_sizes, int n_in,
                              void* d_out, int out_size)
{
    const float* coords = (const float*)d_in[0];
    const float* feats  = (const float*)d_in[1];
    // d_in[2] = k (always 16)
    const float* W1  = (const float*)d_in[3];
    const float* b1  = (const float*)d_in[4];
    const float* g1  = (const float*)d_in[5];
    const float* be1 = (const float*)d_in[6];
    const float* Wa  = (const float*)d_in[7];
    const float* ba  = (const float*)d_in[8];
    const float* ga  = (const float*)d_in[9];
    const float* bea = (const float*)d_in[10];
    const float* W2  = (const float*)d_in[11];
    const float* b2  = (const float*)d_in[12];
    const float* g2  = (const float*)d_in[13];
    const float* be2 = (const float*)d_in[14];
    float* out = (float*)d_out;

    k_knn   <<<dim3(NN/256, BB), 256>>>(coords);
    k_gather<<<ROWS/8, 256>>>(feats);
    k_mlp1  <<<256, 128>>>(W1, b1);
    k_stats1<<<1, MID>>>(g1, be1);
    k_mlpa  <<<256, 128>>>(Wa, ba);
    k_statsa<<<1, MID>>>(ga, bea);
    k_mlp2  <<<256, 128>>>(W2, b2);
    k_stats2<<<1, COUT>>>(g2, be2);
    k_final <<<(ROWS*COUT)/256, 256>>>(out);
}